// round 3
// baseline (speedup 1.0000x reference)
#include <cuda_runtime.h>
#include <math.h>

#define NB 4096
#define NC 62
#define FIN 256
#define NO 64
#define KS 10
#define NTHREADS 512

typedef unsigned long long ull;

__device__ __forceinline__ ull fma2(ull a, ull b, ull c) {
    ull d;
    asm("fma.rn.f32x2 %0, %1, %2, %3;" : "=l"(d) : "l"(a), "l"(b), "l"(c));
    return d;
}
__device__ __forceinline__ ull pack2(float lo, float hi) {
    ull d; asm("mov.b64 %0, {%1,%2};" : "=l"(d) : "f"(lo), "f"(hi)); return d;
}
__device__ __forceinline__ ull bcast2(float v) { return pack2(v, v); }
__device__ __forceinline__ void unpack2(ull d, float& lo, float& hi) {
    asm("mov.b64 {%0,%1}, %2;" : "=f"(lo), "=f"(hi) : "l"(d));
}

// Dynamic smem layout (floats):
// [0, 15872): sx [62][256]  -- dead after phase A; aliased by:
//      sS   @ 0    : [62][64] scores
//      sidx @ 4096 : [62][10] int
//      sval @ 4736 : [62][10] float
// [15872): smask [62][64]
// [19840): sxa   [62][64]
// [23808): sxr   [62][64]   (x @ rel_w1, bias deferred)
// [27776): sxroot[62][64]   (x @ root_w1)
// [31744): sh    [62][64]
// [35712): sagg  [62][64]
// total = 39680 floats = 158720 B

__global__ __launch_bounds__(NTHREADS, 1)
void rg_kernel(const float* __restrict__ x,
               const float* __restrict__ gate_w,  const float* __restrict__ gate_b,
               const float* __restrict__ bnlin_w, const float* __restrict__ bnlin_b,
               const float* __restrict__ rel_w1,  const float* __restrict__ rel_b1,
               const float* __restrict__ root_w1,
               const float* __restrict__ rel_w_mid, const float* __restrict__ rel_b_mid,
               const float* __restrict__ root_w_mid,
               float* __restrict__ out)
{
    extern __shared__ float sm[];
    float* sx     = sm;
    float* sS     = sm;
    int*   sidx   = (int*)(sm + 4096);
    float* sval   = sm + 4736;
    float* smask  = sm + 15872;
    float* sxa    = smask  + NC*NO;
    float* sxr    = sxa    + NC*NO;
    float* sxroot = sxr    + NC*NO;
    float* sh     = sxroot + NC*NO;
    float* sagg   = sh     + NC*NO;

    const int t = threadIdx.x;

    // ---- load x[b] into smem (coalesced float4) ----
    const float* xb = x + (size_t)blockIdx.x * (NC * FIN);
    for (int e = t; e < NC * FIN / 4; e += NTHREADS)
        ((float4*)sx)[e] = ((const float4*)xb)[e];
    __syncthreads();

    // ---- Phase A: 4 projections x[62,256] @ W[256,64], packed f32x2 ----
    // thread map: proj p (t>>7), rowgroup rg ((t>>3)&15) -> rows 4*rg..4*rg+3,
    //             colgroup cg (t&7) -> cols 8*cg..8*cg+7
    {
        int p    = t >> 7;
        int rg   = (t >> 3) & 15;
        int cg   = t & 7;
        int colb = cg * 8;
        const float* W =
            (p == 0 ? gate_w : p == 1 ? bnlin_w : p == 2 ? rel_w1 : root_w1) + colb;

        int rows[4];
        #pragma unroll
        for (int r = 0; r < 4; r++) {
            int i = rg * 4 + r;
            rows[r] = (i < NC) ? i : 0;   // clamp; clamped rows discarded at store
        }

        ull acc[4][4];
        #pragma unroll
        for (int r = 0; r < 4; r++)
            #pragma unroll
            for (int q = 0; q < 4; q++) acc[r][q] = 0ull;

        for (int f = 0; f < FIN; f++) {
            ulonglong2 wa = *(const ulonglong2*)(W + f * NO);       // cols 0..3
            ulonglong2 wb = *(const ulonglong2*)(W + f * NO + 4);   // cols 4..7
            #pragma unroll
            for (int r = 0; r < 4; r++) {
                ull xx = bcast2(sx[rows[r] * FIN + f]);
                acc[r][0] = fma2(xx, wa.x, acc[r][0]);
                acc[r][1] = fma2(xx, wa.y, acc[r][1]);
                acc[r][2] = fma2(xx, wb.x, acc[r][2]);
                acc[r][3] = fma2(xx, wb.y, acc[r][3]);
            }
        }

        float bias[8];
        #pragma unroll
        for (int q = 0; q < 8; q++) bias[q] = 0.f;
        if (p == 0) {
            #pragma unroll
            for (int q = 0; q < 8; q++) bias[q] = gate_b[colb + q];
        } else if (p == 1) {
            #pragma unroll
            for (int q = 0; q < 8; q++) bias[q] = bnlin_b[colb + q];
        }
        float* dst = (p == 0 ? smask : p == 1 ? sxa : p == 2 ? sxr : sxroot);

        #pragma unroll
        for (int r = 0; r < 4; r++) {
            int i = rg * 4 + r;
            if (i < NC) {
                float v[8];
                unpack2(acc[r][0], v[0], v[1]);
                unpack2(acc[r][1], v[2], v[3]);
                unpack2(acc[r][2], v[4], v[5]);
                unpack2(acc[r][3], v[6], v[7]);
                #pragma unroll
                for (int q = 0; q < 8; q++) {
                    v[q] += bias[q];
                    if (p <= 1) v[q] = tanhf(v[q]);
                }
                float4 lo = make_float4(v[0], v[1], v[2], v[3]);
                float4 hi = make_float4(v[4], v[5], v[6], v[7]);
                *(float4*)(dst + i * NO + colb)     = lo;
                *(float4*)(dst + i * NO + colb + 4) = hi;
            }
        }
    }
    __syncthreads();

    // ---- Phase B1: scores S = xa @ xa^T  (62x62, row stride 64) ----
    for (int e = t; e < NC * NC; e += NTHREADS) {
        int i = e / NC, jj = e - i * NC;
        const float4* A  = (const float4*)(sxa + i * NO);
        const float4* Bv = (const float4*)(sxa + jj * NO);
        float acc = 0.f;
        #pragma unroll
        for (int q = 0; q < 16; q++) {
            float4 a = A[q], b = Bv[q];
            acc += a.x * b.x + a.y * b.y + a.z * b.z + a.w * b.w;
        }
        sS[i * NO + jj] = acc;
    }
    __syncthreads();

    // ---- Phase B2: per-row softmax + stable top-10 (tie -> lowest index) ----
    {
        int lane = t & 31;
        int w    = t >> 5;   // 16 warps
        for (int r = w; r < NC; r += 16) {
            float v0 = sS[r * NO + lane];
            float v1 = (lane + 32 < NC) ? sS[r * NO + lane + 32] : -3.4e38f;
            float m = fmaxf(v0, v1);
            #pragma unroll
            for (int off = 16; off; off >>= 1)
                m = fmaxf(m, __shfl_xor_sync(0xffffffffu, m, off));
            float e0 = expf(v0 - m);
            float e1 = (lane + 32 < NC) ? expf(v1 - m) : 0.f;
            float s = e0 + e1;
            #pragma unroll
            for (int off = 16; off; off >>= 1)
                s += __shfl_xor_sync(0xffffffffu, s, off);
            float inv = 1.f / s;
            float c0 = e0 * inv;
            float c1 = (lane + 32 < NC) ? e1 * inv : -1e30f;

            #pragma unroll
            for (int k = 0; k < KS; k++) {
                float bv; int bidx;
                if (c0 >= c1) { bv = c0; bidx = lane; }
                else          { bv = c1; bidx = lane + 32; }
                #pragma unroll
                for (int off = 16; off; off >>= 1) {
                    float ov = __shfl_xor_sync(0xffffffffu, bv, off);
                    int   oi = __shfl_xor_sync(0xffffffffu, bidx, off);
                    if (ov > bv || (ov == bv && oi < bidx)) { bv = ov; bidx = oi; }
                }
                if (lane == 0) { sidx[r * KS + k] = bidx; sval[r * KS + k] = bv; }
                if (bidx == lane)            c0 = -1e30f;
                else if (bidx == lane + 32)  c1 = -1e30f;
            }
        }
    }
    __syncthreads();

    // ---- Phase C: graph conv layers ----
    // thread tile: 2 rows (i0, i0+32) x 4 cols
    int jq = t & 15;           // float4 col index
    int jb = jq * 4;
    int i0 = t >> 4;           // 0..31

    // layer 1: h = relu(adjS @ xr + rel_b1 + xroot)
    {
        float4 b4 = *(const float4*)(rel_b1 + jb);
        #pragma unroll
        for (int r = 0; r < 2; r++) {
            int i = i0 + 32 * r;
            int ii = (i < NC) ? i : 0;
            float4 acc = b4;
            #pragma unroll
            for (int k = 0; k < KS; k++) {
                int   idx = sidx[ii * KS + k];
                float val = sval[ii * KS + k];
                float4 x4 = ((const float4*)(sxr + idx * NO))[jq];
                acc.x += val * x4.x; acc.y += val * x4.y;
                acc.z += val * x4.z; acc.w += val * x4.w;
            }
            float4 ro = ((const float4*)(sxroot + ii * NO))[jq];
            acc.x = fmaxf(acc.x + ro.x, 0.f);
            acc.y = fmaxf(acc.y + ro.y, 0.f);
            acc.z = fmaxf(acc.z + ro.z, 0.f);
            acc.w = fmaxf(acc.w + ro.w, 0.f);
            if (i < NC) ((float4*)(sh + i * NO))[jq] = acc;
        }
    }
    __syncthreads();

    // layers 2..7
    for (int l = 0; l < 6; l++) {
        const float* wrel  = rel_w_mid  + l * NO * NO;
        const float* wroot = root_w_mid + l * NO * NO;
        const float* bb    = rel_b_mid  + l * NO;

        // agg = adjS @ h
        #pragma unroll
        for (int r = 0; r < 2; r++) {
            int i = i0 + 32 * r;
            int ii = (i < NC) ? i : 0;
            float4 acc = make_float4(0.f, 0.f, 0.f, 0.f);
            #pragma unroll
            for (int k = 0; k < KS; k++) {
                int   idx = sidx[ii * KS + k];
                float val = sval[ii * KS + k];
                float4 h4 = ((const float4*)(sh + idx * NO))[jq];
                acc.x += val * h4.x; acc.y += val * h4.y;
                acc.z += val * h4.z; acc.w += val * h4.w;
            }
            if (i < NC) ((float4*)(sagg + i * NO))[jq] = acc;
        }
        __syncthreads();

        // hn = relu(agg @ wrel + b + h @ wroot); residual for l<5  (packed f32x2)
        int iiA = i0;
        int iB  = i0 + 32;
        int iiB = (iB < NC) ? iB : 0;

        float4 b4 = *(const float4*)(bb + jb);
        ull a0p0 = pack2(b4.x, b4.y), a0p1 = pack2(b4.z, b4.w);
        ull a1p0 = a0p0,              a1p1 = a0p1;

        for (int f = 0; f < NO; f++) {
            ulonglong2 wr2 = *(const ulonglong2*)(wrel  + f * NO + jb);
            ulonglong2 wo2 = *(const ulonglong2*)(wroot + f * NO + jb);
            ull av0 = bcast2(sagg[iiA * NO + f]);
            ull hv0 = bcast2(sh  [iiA * NO + f]);
            ull av1 = bcast2(sagg[iiB * NO + f]);
            ull hv1 = bcast2(sh  [iiB * NO + f]);
            a0p0 = fma2(av0, wr2.x, a0p0);
            a0p1 = fma2(av0, wr2.y, a0p1);
            a0p0 = fma2(hv0, wo2.x, a0p0);
            a0p1 = fma2(hv0, wo2.y, a0p1);
            a1p0 = fma2(av1, wr2.x, a1p0);
            a1p1 = fma2(av1, wr2.y, a1p1);
            a1p0 = fma2(hv1, wo2.x, a1p0);
            a1p1 = fma2(hv1, wo2.y, a1p1);
        }

        float4 a0, a1;
        unpack2(a0p0, a0.x, a0.y); unpack2(a0p1, a0.z, a0.w);
        unpack2(a1p0, a1.x, a1.y); unpack2(a1p1, a1.z, a1.w);

        float4 hn0, hn1;
        {
            float4 h4 = ((const float4*)(sh + iiA * NO))[jq];
            hn0.x = fmaxf(a0.x, 0.f); hn0.y = fmaxf(a0.y, 0.f);
            hn0.z = fmaxf(a0.z, 0.f); hn0.w = fmaxf(a0.w, 0.f);
            if (l < 5) { hn0.x += h4.x; hn0.y += h4.y; hn0.z += h4.z; hn0.w += h4.w; }
        }
        {
            float4 h4 = ((const float4*)(sh + iiB * NO))[jq];
            hn1.x = fmaxf(a1.x, 0.f); hn1.y = fmaxf(a1.y, 0.f);
            hn1.z = fmaxf(a1.z, 0.f); hn1.w = fmaxf(a1.w, 0.f);
            if (l < 5) { hn1.x += h4.x; hn1.y += h4.y; hn1.z += h4.z; hn1.w += h4.w; }
        }
        __syncthreads();   // all reads of sh/sagg complete
        if (i0 < NC)      ((float4*)(sh + i0 * NO))[jq] = hn0;
        if (i0 + 32 < NC) ((float4*)(sh + (i0 + 32) * NO))[jq] = hn1;
        __syncthreads();
    }

    // ---- output: h * mask ----
    float* ob = out + (size_t)blockIdx.x * (NC * NO);
    for (int e = t; e < NC * NO / 4; e += NTHREADS) {
        float4 h4 = ((const float4*)sh)[e];
        float4 m4 = ((const float4*)smask)[e];
        float4 v;
        v.x = h4.x * m4.x; v.y = h4.y * m4.y;
        v.z = h4.z * m4.z; v.w = h4.w * m4.w;
        ((float4*)ob)[e] = v;
    }
}

extern "C" void kernel_launch(void* const* d_in, const int* in_sizes, int n_in,
                              void* d_out, int out_size)
{
    const size_t smem = 39680 * sizeof(float);   // 158720 B
    (void)cudaFuncSetAttribute(rg_kernel, cudaFuncAttributeMaxDynamicSharedMemorySize, (int)smem);
    rg_kernel<<<NB, NTHREADS, smem>>>(
        (const float*)d_in[0],  (const float*)d_in[1],  (const float*)d_in[2],
        (const float*)d_in[3],  (const float*)d_in[4],  (const float*)d_in[5],
        (const float*)d_in[6],  (const float*)d_in[7],  (const float*)d_in[8],
        (const float*)d_in[9],  (const float*)d_in[10], (float*)d_out);
}

// round 4
// speedup vs baseline: 1.0073x; 1.0073x over previous
#include <cuda_runtime.h>
#include <math.h>

#define NB 4096
#define NC 62
#define FIN 256
#define NO 64
#define KS 10
#define NTHREADS 512

typedef unsigned long long ull;

__device__ __forceinline__ ull fma2(ull a, ull b, ull c) {
    ull d;
    asm("fma.rn.f32x2 %0, %1, %2, %3;" : "=l"(d) : "l"(a), "l"(b), "l"(c));
    return d;
}
__device__ __forceinline__ ull pack2(float lo, float hi) {
    ull d; asm("mov.b64 %0, {%1,%2};" : "=l"(d) : "f"(lo), "f"(hi)); return d;
}
__device__ __forceinline__ ull bcast2(float v) { return pack2(v, v); }
__device__ __forceinline__ void unpack2(ull d, float& lo, float& hi) {
    asm("mov.b64 {%0,%1}, %2;" : "=f"(lo), "=f"(hi) : "l"(d));
}
__device__ __forceinline__ float comp4(const float4& v, int u) {
    return u == 0 ? v.x : u == 1 ? v.y : u == 2 ? v.z : v.w;
}

// Dynamic smem layout (floats):
// [0, 15872): sx [62][256]  -- dead after phase A; aliased by:
//      sS   @ 0    : [62][64] scores
//      sidx @ 4096 : [62][10] int
//      sval @ 4736 : [62][10] float
// [15872): smask [62][64]
// [19840): sxa   [62][64]
// [23808): sxr   [62][64]
// [27776): sxroot[62][64]
// [31744): sh    [62][64]
// [35712): sagg  [62][64]
// total = 39680 floats = 158720 B

__global__ __launch_bounds__(NTHREADS, 1)
void rg_kernel(const float* __restrict__ x,
               const float* __restrict__ gate_w,  const float* __restrict__ gate_b,
               const float* __restrict__ bnlin_w, const float* __restrict__ bnlin_b,
               const float* __restrict__ rel_w1,  const float* __restrict__ rel_b1,
               const float* __restrict__ root_w1,
               const float* __restrict__ rel_w_mid, const float* __restrict__ rel_b_mid,
               const float* __restrict__ root_w_mid,
               float* __restrict__ out)
{
    extern __shared__ float sm[];
    float* sx     = sm;
    float* sS     = sm;
    int*   sidx   = (int*)(sm + 4096);
    float* sval   = sm + 4736;
    float* smask  = sm + 15872;
    float* sxa    = smask  + NC*NO;
    float* sxr    = sxa    + NC*NO;
    float* sxroot = sxr    + NC*NO;
    float* sh     = sxroot + NC*NO;
    float* sagg   = sh     + NC*NO;

    const int t = threadIdx.x;

    // ---- load x[b] into smem (coalesced float4) ----
    const float* xb = x + (size_t)blockIdx.x * (NC * FIN);
    for (int e = t; e < NC * FIN / 4; e += NTHREADS)
        ((float4*)sx)[e] = ((const float4*)xb)[e];
    __syncthreads();

    // ---- Phase A: 4 projections x[62,256] @ W[256,64], packed f32x2 ----
    // thread map: proj p (t>>7), rowgroup rg ((t>>3)&15) -> rows 4*rg..+3,
    //             colgroup cg (t&7) -> cols 8*cg..+7
    {
        int p    = t >> 7;
        int rg   = (t >> 3) & 15;
        int cg   = t & 7;
        int colb = cg * 8;
        const float* W =
            (p == 0 ? gate_w : p == 1 ? bnlin_w : p == 2 ? rel_w1 : root_w1) + colb;

        int rows[4];
        #pragma unroll
        for (int r = 0; r < 4; r++) {
            int i = rg * 4 + r;
            rows[r] = (i < NC) ? i : 0;   // clamped rows discarded at store
        }

        ull acc[4][4];
        #pragma unroll
        for (int r = 0; r < 4; r++)
            #pragma unroll
            for (int q = 0; q < 4; q++) acc[r][q] = 0ull;

        for (int f4 = 0; f4 < FIN / 4; f4++) {
            float4 x4[4];
            #pragma unroll
            for (int r = 0; r < 4; r++)
                x4[r] = *(const float4*)(sx + rows[r] * FIN + f4 * 4);
            #pragma unroll
            for (int u = 0; u < 4; u++) {
                const float* Wf = W + (f4 * 4 + u) * NO;
                ulonglong2 wa = *(const ulonglong2*)(Wf);
                ulonglong2 wb = *(const ulonglong2*)(Wf + 4);
                #pragma unroll
                for (int r = 0; r < 4; r++) {
                    ull xx = bcast2(comp4(x4[r], u));
                    acc[r][0] = fma2(xx, wa.x, acc[r][0]);
                    acc[r][1] = fma2(xx, wa.y, acc[r][1]);
                    acc[r][2] = fma2(xx, wb.x, acc[r][2]);
                    acc[r][3] = fma2(xx, wb.y, acc[r][3]);
                }
            }
        }

        float bias[8];
        #pragma unroll
        for (int q = 0; q < 8; q++) bias[q] = 0.f;
        if (p == 0) {
            #pragma unroll
            for (int q = 0; q < 8; q++) bias[q] = gate_b[colb + q];
        } else if (p == 1) {
            #pragma unroll
            for (int q = 0; q < 8; q++) bias[q] = bnlin_b[colb + q];
        }
        float* dst = (p == 0 ? smask : p == 1 ? sxa : p == 2 ? sxr : sxroot);

        #pragma unroll
        for (int r = 0; r < 4; r++) {
            int i = rg * 4 + r;
            if (i < NC) {
                float v[8];
                unpack2(acc[r][0], v[0], v[1]);
                unpack2(acc[r][1], v[2], v[3]);
                unpack2(acc[r][2], v[4], v[5]);
                unpack2(acc[r][3], v[6], v[7]);
                #pragma unroll
                for (int q = 0; q < 8; q++) {
                    v[q] += bias[q];
                    if (p <= 1) v[q] = tanhf(v[q]);
                }
                *(float4*)(dst + i * NO + colb)     = make_float4(v[0], v[1], v[2], v[3]);
                *(float4*)(dst + i * NO + colb + 4) = make_float4(v[4], v[5], v[6], v[7]);
            }
        }
    }
    __syncthreads();

    // ---- Phase B1: scores S = xa @ xa^T ----
    // thread map: row i = t>>3 (0..63), j-block = (t&7)*8 -> 8 j's per thread.
    // A row float4 reused across 8 accumulators.
    {
        int i   = t >> 3;
        int ii  = (i < NC) ? i : 0;
        int jb0 = (t & 7) * 8;
        float accj[8];
        #pragma unroll
        for (int jj = 0; jj < 8; jj++) accj[jj] = 0.f;

        const float4* A = (const float4*)(sxa + ii * NO);
        #pragma unroll
        for (int q = 0; q < 16; q++) {
            float4 a4 = A[q];
            #pragma unroll
            for (int jj = 0; jj < 8; jj++) {
                int j  = jb0 + jj;
                int jc = (j < NC) ? j : 0;
                float4 b4 = ((const float4*)(sxa + jc * NO))[q];
                accj[jj] += a4.x * b4.x + a4.y * b4.y + a4.z * b4.z + a4.w * b4.w;
            }
        }
        if (i < NC) {
            #pragma unroll
            for (int jj = 0; jj < 8; jj++) {
                int j = jb0 + jj;
                if (j < NC) sS[i * NO + j] = accj[jj];
            }
        }
    }
    __syncthreads();

    // ---- Phase B2: per-row softmax + stable top-10 (tie -> lowest index) ----
    {
        int lane = t & 31;
        int w    = t >> 5;   // 16 warps
        for (int r = w; r < NC; r += 16) {
            float v0 = sS[r * NO + lane];
            float v1 = (lane + 32 < NC) ? sS[r * NO + lane + 32] : -3.4e38f;
            float m = fmaxf(v0, v1);
            #pragma unroll
            for (int off = 16; off; off >>= 1)
                m = fmaxf(m, __shfl_xor_sync(0xffffffffu, m, off));
            float e0 = expf(v0 - m);
            float e1 = (lane + 32 < NC) ? expf(v1 - m) : 0.f;
            float s = e0 + e1;
            #pragma unroll
            for (int off = 16; off; off >>= 1)
                s += __shfl_xor_sync(0xffffffffu, s, off);
            float inv = 1.f / s;
            float c0 = e0 * inv;
            float c1 = (lane + 32 < NC) ? e1 * inv : -1e30f;

            #pragma unroll
            for (int k = 0; k < KS; k++) {
                float bv; int bidx;
                if (c0 >= c1) { bv = c0; bidx = lane; }
                else          { bv = c1; bidx = lane + 32; }
                #pragma unroll
                for (int off = 16; off; off >>= 1) {
                    float ov = __shfl_xor_sync(0xffffffffu, bv, off);
                    int   oi = __shfl_xor_sync(0xffffffffu, bidx, off);
                    if (ov > bv || (ov == bv && oi < bidx)) { bv = ov; bidx = oi; }
                }
                if (lane == 0) { sidx[r * KS + k] = bidx; sval[r * KS + k] = bv; }
                if (bidx == lane)            c0 = -1e30f;
                else if (bidx == lane + 32)  c1 = -1e30f;
            }
        }
    }
    __syncthreads();

    // ---- Phase C: graph conv layers ----
    // thread tile: 2 rows (i0, i0+32) x 4 cols
    int jq = t & 15;           // float4 col index
    int jb = jq * 4;
    int i0 = t >> 4;           // 0..31

    // layer 1: h = relu(adjS @ xr + rel_b1 + xroot)
    {
        float4 b4 = *(const float4*)(rel_b1 + jb);
        #pragma unroll
        for (int r = 0; r < 2; r++) {
            int i = i0 + 32 * r;
            int ii = (i < NC) ? i : 0;
            float4 acc = b4;
            #pragma unroll
            for (int k = 0; k < KS; k++) {
                int   idx = sidx[ii * KS + k];
                float val = sval[ii * KS + k];
                float4 x4 = ((const float4*)(sxr + idx * NO))[jq];
                acc.x += val * x4.x; acc.y += val * x4.y;
                acc.z += val * x4.z; acc.w += val * x4.w;
            }
            float4 ro = ((const float4*)(sxroot + ii * NO))[jq];
            acc.x = fmaxf(acc.x + ro.x, 0.f);
            acc.y = fmaxf(acc.y + ro.y, 0.f);
            acc.z = fmaxf(acc.z + ro.z, 0.f);
            acc.w = fmaxf(acc.w + ro.w, 0.f);
            if (i < NC) ((float4*)(sh + i * NO))[jq] = acc;
        }
    }
    __syncthreads();

    // layers 2..7
    for (int l = 0; l < 6; l++) {
        const float* wrel  = rel_w_mid  + l * NO * NO;
        const float* wroot = root_w_mid + l * NO * NO;
        const float* bb    = rel_b_mid  + l * NO;

        // agg = adjS @ h
        #pragma unroll
        for (int r = 0; r < 2; r++) {
            int i = i0 + 32 * r;
            int ii = (i < NC) ? i : 0;
            float4 acc = make_float4(0.f, 0.f, 0.f, 0.f);
            #pragma unroll
            for (int k = 0; k < KS; k++) {
                int   idx = sidx[ii * KS + k];
                float val = sval[ii * KS + k];
                float4 h4 = ((const float4*)(sh + idx * NO))[jq];
                acc.x += val * h4.x; acc.y += val * h4.y;
                acc.z += val * h4.z; acc.w += val * h4.w;
            }
            if (i < NC) ((float4*)(sagg + i * NO))[jq] = acc;
        }
        __syncthreads();

        // hn = relu(agg @ wrel + b + h @ wroot); residual for l<5
        // packed f32x2, activation operands vectorized over f by 4
        int iiA = i0;
        int iB  = i0 + 32;
        int iiB = (iB < NC) ? iB : 0;

        float4 b4 = *(const float4*)(bb + jb);
        ull a0p0 = pack2(b4.x, b4.y), a0p1 = pack2(b4.z, b4.w);
        ull a1p0 = a0p0,              a1p1 = a0p1;

        for (int f4 = 0; f4 < NO / 4; f4++) {
            float4 av0 = *(const float4*)(sagg + iiA * NO + f4 * 4);
            float4 hv0 = *(const float4*)(sh   + iiA * NO + f4 * 4);
            float4 av1 = *(const float4*)(sagg + iiB * NO + f4 * 4);
            float4 hv1 = *(const float4*)(sh   + iiB * NO + f4 * 4);
            #pragma unroll
            for (int u = 0; u < 4; u++) {
                int f = f4 * 4 + u;
                ulonglong2 wr2 = *(const ulonglong2*)(wrel  + f * NO + jb);
                ulonglong2 wo2 = *(const ulonglong2*)(wroot + f * NO + jb);
                ull a0 = bcast2(comp4(av0, u));
                ull h0 = bcast2(comp4(hv0, u));
                ull a1 = bcast2(comp4(av1, u));
                ull h1 = bcast2(comp4(hv1, u));
                a0p0 = fma2(a0, wr2.x, a0p0);
                a0p1 = fma2(a0, wr2.y, a0p1);
                a0p0 = fma2(h0, wo2.x, a0p0);
                a0p1 = fma2(h0, wo2.y, a0p1);
                a1p0 = fma2(a1, wr2.x, a1p0);
                a1p1 = fma2(a1, wr2.y, a1p1);
                a1p0 = fma2(h1, wo2.x, a1p0);
                a1p1 = fma2(h1, wo2.y, a1p1);
            }
        }

        float4 a0, a1;
        unpack2(a0p0, a0.x, a0.y); unpack2(a0p1, a0.z, a0.w);
        unpack2(a1p0, a1.x, a1.y); unpack2(a1p1, a1.z, a1.w);

        float4 hn0, hn1;
        {
            float4 h4 = ((const float4*)(sh + iiA * NO))[jq];
            hn0.x = fmaxf(a0.x, 0.f); hn0.y = fmaxf(a0.y, 0.f);
            hn0.z = fmaxf(a0.z, 0.f); hn0.w = fmaxf(a0.w, 0.f);
            if (l < 5) { hn0.x += h4.x; hn0.y += h4.y; hn0.z += h4.z; hn0.w += h4.w; }
        }
        {
            float4 h4 = ((const float4*)(sh + iiB * NO))[jq];
            hn1.x = fmaxf(a1.x, 0.f); hn1.y = fmaxf(a1.y, 0.f);
            hn1.z = fmaxf(a1.z, 0.f); hn1.w = fmaxf(a1.w, 0.f);
            if (l < 5) { hn1.x += h4.x; hn1.y += h4.y; hn1.z += h4.z; hn1.w += h4.w; }
        }
        __syncthreads();   // all reads of sh/sagg complete
        if (i0 < NC)      ((float4*)(sh + i0 * NO))[jq] = hn0;
        if (i0 + 32 < NC) ((float4*)(sh + (i0 + 32) * NO))[jq] = hn1;
        __syncthreads();
    }

    // ---- output: h * mask ----
    float* ob = out + (size_t)blockIdx.x * (NC * NO);
    for (int e = t; e < NC * NO / 4; e += NTHREADS) {
        float4 h4 = ((const float4*)sh)[e];
        float4 m4 = ((const float4*)smask)[e];
        float4 v;
        v.x = h4.x * m4.x; v.y = h4.y * m4.y;
        v.z = h4.z * m4.z; v.w = h4.w * m4.w;
        ((float4*)ob)[e] = v;
    }
}

extern "C" void kernel_launch(void* const* d_in, const int* in_sizes, int n_in,
                              void* d_out, int out_size)
{
    const size_t smem = 39680 * sizeof(float);   // 158720 B
    (void)cudaFuncSetAttribute(rg_kernel, cudaFuncAttributeMaxDynamicSharedMemorySize, (int)smem);
    rg_kernel<<<NB, NTHREADS, smem>>>(
        (const float*)d_in[0],  (const float*)d_in[1],  (const float*)d_in[2],
        (const float*)d_in[3],  (const float*)d_in[4],  (const float*)d_in[5],
        (const float*)d_in[6],  (const float*)d_in[7],  (const float*)d_in[8],
        (const float*)d_in[9],  (const float*)d_in[10], (float*)d_out);
}